// round 6
// baseline (speedup 1.0000x reference)
#include <cuda_runtime.h>
#include <math_constants.h>

// Prefix-max (cumulative max) along H for x of shape (B=32, C=1, H=1024, W=1024), fp32.
// Layout: x[(b*H + h)*W + w]. 32768 independent columns (b,w), scan length H=1024.
//
// Tile: 512-thread block owns 32 consecutive float-columns x full H.
// Warp = 32 lanes over 32 consecutive columns, same chunk -> every LDG/STG is
// one fully-used 128B line (vs two 64B sectors in the previous version).
// H processed as 4 quarters of 256 rows: 16 chunks x 16 rows/thread each
// (v[16] -> ~40 regs -> 3 CTAs/SM via __launch_bounds__(512, 3)).
// Per quarter: coalesced loads, local prefix-max, chunk totals -> smem
// (1 barrier), each warp shuffle-scans 2 columns with width-16 shuffles
// (4 rounds, no barrier), read-back (1 barrier), apply carry, coalesced stores.
// Double-buffered smem: 2 barriers per quarter, 8 total.

#define H_DIM 1024
#define W_DIM 1024
#define COLS_PER_BLOCK 32
#define CHUNKS 16
#define ROWS_PER_THREAD 16    // per quarter
#define QUARTER_ROWS 256      // CHUNKS * ROWS_PER_THREAD
#define NUM_QUARTERS 4

__global__ __launch_bounds__(512, 3)
void cummax_kernel(const float* __restrict__ x, float* __restrict__ out) {
    const int tid   = threadIdx.x;
    const int c     = tid & (COLS_PER_BLOCK - 1);   // 0..31
    const int chunk = tid >> 5;                     // 0..15
    const int wid   = tid >> 5;                     // warp id == chunk here
    const int lane  = tid & 31;

    const int col = blockIdx.x * COLS_PER_BLOCK + c;  // 1024 % 32 == 0: no b straddle
    const int b   = col >> 10;
    const int w   = col & (W_DIM - 1);

    const int base0 = b * (H_DIM * W_DIM) + w + chunk * ROWS_PER_THREAD * W_DIM;

    __shared__ float s[2][CHUNKS][COLS_PER_BLOCK + 1];   // double buffer, padded

    // Warp-scan lane mapping: warp `wid` scans columns 2*wid and 2*wid+1;
    // lanes 0-15 hold chunks 0-15 of col 2*wid, lanes 16-31 of col 2*wid+1.
    const int scan_col = 2 * wid + (lane >> 4);
    const int scan_ch  = lane & 15;

    float carry = -CUDART_INF_F;

#pragma unroll
    for (int q = 0; q < NUM_QUARTERS; q++) {
        const int buf  = q & 1;
        const int base = base0 + q * QUARTER_ROWS * W_DIM;
        const float* __restrict__ src = x   + base;
        float*       __restrict__ dst = out + base;

        // Load 16 rows: each warp-load is one contiguous 128B line.
        float v[ROWS_PER_THREAD];
#pragma unroll
        for (int i = 0; i < ROWS_PER_THREAD; i++) {
            v[i] = src[i * W_DIM];
        }
#pragma unroll
        for (int i = 1; i < ROWS_PER_THREAD; i++) {
            v[i] = fmaxf(v[i], v[i - 1]);
        }

        // Cross-chunk inclusive max-scan of totals (width-16 warp shuffles).
        s[buf][chunk][c] = v[ROWS_PER_THREAD - 1];
        __syncthreads();

        {
            float t = s[buf][scan_ch][scan_col];
#pragma unroll
            for (int d = 1; d < 16; d <<= 1) {
                float o = __shfl_up_sync(0xFFFFFFFFu, t, d, 16);
                if (scan_ch >= d) t = fmaxf(t, o);
            }
            s[buf][scan_ch][scan_col] = t;
        }
        __syncthreads();

        // Exclusive carry: preceding chunks of this quarter + previous quarters.
        const float excl = (chunk > 0) ? s[buf][chunk - 1][c] : -CUDART_INF_F;
        const float m = fmaxf(carry, excl);

#pragma unroll
        for (int i = 0; i < ROWS_PER_THREAD; i++) {
            dst[i * W_DIM] = fmaxf(v[i], m);
        }

        carry = fmaxf(carry, s[buf][CHUNKS - 1][c]);
    }
}

extern "C" void kernel_launch(void* const* d_in, const int* in_sizes, int n_in,
                              void* d_out, int out_size) {
    const float* x = (const float*)d_in[0];
    float* out = (float*)d_out;

    const int total_cols = 32 * W_DIM;                        // 32768
    const int grid = total_cols / COLS_PER_BLOCK;             // 1024
    cummax_kernel<<<grid, 512>>>(x, out);
}

// round 7
// speedup vs baseline: 1.0581x; 1.0581x over previous
#include <cuda_runtime.h>
#include <math_constants.h>

// Prefix-max (cumulative max) along H for x of shape (B=32, C=1, H=1024, W=1024), fp32.
// Layout: x[(b*H + h)*W + w]. 32768 independent columns (b,w), scan length H=1024.
//
// Geometry (best scored, from R5): 512-thread block owns 16 consecutive
// float-columns x full H; 64B warp segments; grid 2048.
// New in this round: 4 passes of 8 rows/thread (v[8]) to fit <=32 regs and
// run 4 CTAs/SM (__launch_bounds__(512, 4)) -> 64 warps resident, deeper
// phase interleaving and softer wave tail.
//   thread t: c = t & 15, chunk = t >> 4 (32 chunks of 8 rows per pass).
//   Per pass: coalesced loads, local prefix-max, chunk totals -> smem
//   (1 barrier), warp-per-column shuffle scan (5 rounds, no barrier),
//   read-back (1 barrier), apply carry (incl. cross-pass), coalesced stores.
// Double-buffered smem: 2 barriers per pass, 8 total.

#define H_DIM 1024
#define W_DIM 1024
#define COLS_PER_BLOCK 16
#define CHUNKS 32
#define ROWS_PER_THREAD 8     // per pass
#define PASS_ROWS 256         // CHUNKS * ROWS_PER_THREAD
#define NUM_PASSES 4

__global__ __launch_bounds__(512, 4)
void cummax_kernel(const float* __restrict__ x, float* __restrict__ out) {
    const int tid   = threadIdx.x;
    const int c     = tid & (COLS_PER_BLOCK - 1);   // 0..15
    const int chunk = tid >> 4;                     // 0..31
    const int wid   = tid >> 5;                     // 0..15
    const int lane  = tid & 31;

    const int col = blockIdx.x * COLS_PER_BLOCK + c;  // 1024 % 16 == 0: no b straddle
    const int b   = col >> 10;
    const int w   = col & (W_DIM - 1);

    const int base0 = b * (H_DIM * W_DIM) + w + chunk * ROWS_PER_THREAD * W_DIM;

    __shared__ float s[2][CHUNKS][COLS_PER_BLOCK + 1];   // double buffer, padded

    float carry = -CUDART_INF_F;

#pragma unroll
    for (int p = 0; p < NUM_PASSES; p++) {
        const int buf  = p & 1;
        const int base = base0 + p * PASS_ROWS * W_DIM;
        const float* __restrict__ src = x   + base;
        float*       __restrict__ dst = out + base;

        // Load 8 rows (coalesced: warp covers 2 rows x 64B fully-used segments).
        float v[ROWS_PER_THREAD];
#pragma unroll
        for (int i = 0; i < ROWS_PER_THREAD; i++) {
            v[i] = src[i * W_DIM];
        }
#pragma unroll
        for (int i = 1; i < ROWS_PER_THREAD; i++) {
            v[i] = fmaxf(v[i], v[i - 1]);
        }

        // Cross-chunk inclusive max-scan of totals via warp shuffles.
        s[buf][chunk][c] = v[ROWS_PER_THREAD - 1];
        __syncthreads();

        // Warp `wid` scans column `wid`: lane = chunk index. 16 warps, 16 cols.
        {
            float t = s[buf][lane][wid];
#pragma unroll
            for (int d = 1; d < 32; d <<= 1) {
                float o = __shfl_up_sync(0xFFFFFFFFu, t, d);
                if (lane >= d) t = fmaxf(t, o);
            }
            s[buf][lane][wid] = t;
        }
        __syncthreads();

        // Exclusive carry: preceding chunks of this pass + previous passes.
        const float excl = (chunk > 0) ? s[buf][chunk - 1][c] : -CUDART_INF_F;
        const float m = fmaxf(carry, excl);

#pragma unroll
        for (int i = 0; i < ROWS_PER_THREAD; i++) {
            dst[i * W_DIM] = fmaxf(v[i], m);
        }

        carry = fmaxf(carry, s[buf][CHUNKS - 1][c]);
    }
}

extern "C" void kernel_launch(void* const* d_in, const int* in_sizes, int n_in,
                              void* d_out, int out_size) {
    const float* x = (const float*)d_in[0];
    float* out = (float*)d_out;

    const int total_cols = 32 * W_DIM;                        // 32768
    const int grid = total_cols / COLS_PER_BLOCK;             // 2048
    cummax_kernel<<<grid, 512>>>(x, out);
}